// round 9
// baseline (speedup 1.0000x reference)
#include <cuda_runtime.h>
#include <cuda_fp16.h>
#include <cstdint>

#define B_ 16
#define S_ 2048
#define D_ 128
#define SCALE_ 0.08838834764831845f  // 1/sqrt(128)

#define HLD_ 48    // halves per smem row (32 data + 16 pad) = 24 words
#define VLD_ 136   // words per Vs2 row (128 data + 8 pad)
#define NT_ 16     // number of 128-wide column tiles per row

// per-(row,tile) softmax partials (m_t, s_t) and final scales
__device__ float2 g_stats[(size_t)B_ * S_ * NT_];   // 4 MB
__device__ float  g_scale[(size_t)B_ * S_ * NT_];   // 2 MB

__device__ __forceinline__ uint32_t h2u(half2 h) {
    union { half2 h; uint32_t u; } cvt;
    cvt.h = h;
    return cvt.u;
}

// D += A*B, m16n8k16 f16 (f32 accum)
__device__ __forceinline__ void mma16(float* d, uint32_t a0, uint32_t a1, uint32_t a2,
                                      uint32_t a3, uint32_t b0, uint32_t b1) {
    asm volatile(
        "mma.sync.aligned.m16n8k16.row.col.f32.f16.f16.f32 "
        "{%0,%1,%2,%3}, {%4,%5,%6,%7}, {%8,%9}, {%0,%1,%2,%3};"
        : "+f"(d[0]), "+f"(d[1]), "+f"(d[2]), "+f"(d[3])
        : "r"(a0), "r"(a1), "r"(a2), "r"(a3), "r"(b0), "r"(b1));
}

// Permuted half store: within each 16-k group, k=2c+h+8e -> pos 4c+2e+h.
__device__ __forceinline__ void store_perm(half* rowp, int c4, float4 v) {
    const int kk0 = c4 & 15;
    const int pos = ((c4 >> 4) << 4) + ((kk0 & 7) << 1) + ((kk0 >> 3) << 1);
    *(half2*)(rowp + pos)     = __floats2half2_rn(v.x, v.y);
    *(half2*)(rowp + pos + 4) = __floats2half2_rn(v.z, v.w);
}

// =====================================================================
// Kernel 1: e[b,q,k] = exp((Q.K^T)*SCALE + mask - m_tile) ; writes
// per-(row,tile) stats (m_t, s_t). CTA 128x128, fp16 m16n8k16.
// =====================================================================
__global__ __launch_bounds__(256, 2) void scores_mma(
    const float* __restrict__ q, const float* __restrict__ k,
    const float* __restrict__ mask, float* __restrict__ attn)
{
    __shared__ half Qh[128 * HLD_];
    __shared__ half Kh[128 * HLD_];
    __shared__ float rowred[128][4];

    const int b  = blockIdx.x;
    const int kt = blockIdx.y * 128;
    const int qt = blockIdx.z * 128;

    const float* qb = q + ((size_t)b * S_ + qt) * D_;
    const float* kb = k + ((size_t)b * S_ + kt) * D_;

    const int tid  = threadIdx.x;
    const int wid  = tid >> 5, lane = tid & 31;
    const int g    = lane >> 2, c = lane & 3;
    const int wm   = (wid & 1) * 64;
    const int wn   = (wid >> 1) * 32;
    const int widn = wid >> 1;

    float acc[4][4][4];
#pragma unroll
    for (int mi = 0; mi < 4; mi++)
#pragma unroll
        for (int ni = 0; ni < 4; ni++)
#pragma unroll
            for (int r = 0; r < 4; r++) acc[mi][ni][r] = 0.0f;

#pragma unroll 1
    for (int d0 = 0; d0 < D_; d0 += 32) {
#pragma unroll
        for (int t = 0; t < 4; t++) {
            const int idx = tid + t * 256;
            const int row = idx >> 3, c4 = (idx & 7) * 4;
            const float4 vq = *(const float4*)&qb[(size_t)row * D_ + d0 + c4];
            const float4 vk = *(const float4*)&kb[(size_t)row * D_ + d0 + c4];
            store_perm(&Qh[row * HLD_], c4, vq);
            store_perm(&Kh[row * HLD_], c4, vk);
        }
        __syncthreads();

#pragma unroll
        for (int kq = 0; kq < 2; kq++) {
            const int co = kq * 16 + 4 * c;
            uint2 bf[4];
#pragma unroll
            for (int ni = 0; ni < 4; ni++)
                bf[ni] = *(const uint2*)&Kh[(wn + ni * 8 + g) * HLD_ + co];
#pragma unroll
            for (int mi = 0; mi < 4; mi++) {
                const int row = wm + mi * 16 + g;
                const uint2 alo = *(const uint2*)&Qh[row * HLD_ + co];
                const uint2 ahi = *(const uint2*)&Qh[(row + 8) * HLD_ + co];
#pragma unroll
                for (int ni = 0; ni < 4; ni++)
                    mma16(acc[mi][ni], alo.x, ahi.x, alo.y, ahi.y, bf[ni].x, bf[ni].y);
            }
        }
        __syncthreads();
    }

    // ---- Epilogue: scale + mask into acc ----
#pragma unroll
    for (int mi = 0; mi < 4; mi++) {
#pragma unroll
        for (int rr = 0; rr < 2; rr++) {
            const int qrow = qt + wm + mi * 16 + g + rr * 8;
            const float* mrow_p = mask + (size_t)qrow * S_ + kt;
#pragma unroll
            for (int ni = 0; ni < 4; ni++) {
                const float2 m2 = *(const float2*)&mrow_p[wn + ni * 8 + c * 2];
                acc[mi][ni][rr * 2 + 0] = acc[mi][ni][rr * 2 + 0] * SCALE_ + m2.x;
                acc[mi][ni][rr * 2 + 1] = acc[mi][ni][rr * 2 + 1] * SCALE_ + m2.y;
            }
        }
    }

    // ---- Per-row tile max ----
    float rmax[4][2];
#pragma unroll
    for (int mi = 0; mi < 4; mi++)
#pragma unroll
        for (int rr = 0; rr < 2; rr++) {
            float m = acc[mi][0][rr * 2];
#pragma unroll
            for (int ni = 0; ni < 4; ni++) {
                m = fmaxf(m, acc[mi][ni][rr * 2 + 0]);
                m = fmaxf(m, acc[mi][ni][rr * 2 + 1]);
            }
            m = fmaxf(m, __shfl_xor_sync(0xFFFFFFFF, m, 1));
            m = fmaxf(m, __shfl_xor_sync(0xFFFFFFFF, m, 2));
            rmax[mi][rr] = m;
        }
    if (c == 0) {
#pragma unroll
        for (int mi = 0; mi < 4; mi++)
#pragma unroll
            for (int rr = 0; rr < 2; rr++)
                rowred[wm + mi * 16 + g + rr * 8][widn] = rmax[mi][rr];
    }
    __syncthreads();

    float mrow[4][2];
#pragma unroll
    for (int mi = 0; mi < 4; mi++)
#pragma unroll
        for (int rr = 0; rr < 2; rr++) {
            const int row = wm + mi * 16 + g + rr * 8;
            mrow[mi][rr] = fmaxf(fmaxf(rowred[row][0], rowred[row][1]),
                                 fmaxf(rowred[row][2], rowred[row][3]));
        }
    __syncthreads();

    // ---- exp + per-row tile sum ----
    float rsum[4][2];
#pragma unroll
    for (int mi = 0; mi < 4; mi++)
#pragma unroll
        for (int rr = 0; rr < 2; rr++) {
            const float m = mrow[mi][rr];
            float s = 0.0f;
#pragma unroll
            for (int ni = 0; ni < 4; ni++) {
                float e0 = __expf(acc[mi][ni][rr * 2 + 0] - m);
                float e1 = __expf(acc[mi][ni][rr * 2 + 1] - m);
                acc[mi][ni][rr * 2 + 0] = e0;
                acc[mi][ni][rr * 2 + 1] = e1;
                s += e0 + e1;
            }
            s += __shfl_xor_sync(0xFFFFFFFF, s, 1);
            s += __shfl_xor_sync(0xFFFFFFFF, s, 2);
            rsum[mi][rr] = s;
        }
    if (c == 0) {
#pragma unroll
        for (int mi = 0; mi < 4; mi++)
#pragma unroll
            for (int rr = 0; rr < 2; rr++)
                rowred[wm + mi * 16 + g + rr * 8][widn] = rsum[mi][rr];
    }
    __syncthreads();

    // one warp-pair writes stats (warps 0,1 cover all 128 rows, lanes c==0)
    if (widn == 0 && c == 0) {
#pragma unroll
        for (int mi = 0; mi < 4; mi++)
#pragma unroll
            for (int rr = 0; rr < 2; rr++) {
                const int lrow = wm + mi * 16 + g + rr * 8;
                const float s = rowred[lrow][0] + rowred[lrow][1] +
                                rowred[lrow][2] + rowred[lrow][3];
                g_stats[((size_t)(b * S_ + qt + lrow)) * NT_ + blockIdx.y] =
                    make_float2(mrow[mi][rr], s);
            }
    }

    // ---- write e to attn ----
#pragma unroll
    for (int mi = 0; mi < 4; mi++) {
#pragma unroll
        for (int rr = 0; rr < 2; rr++) {
            const int qrow = qt + wm + mi * 16 + g + rr * 8;
            float* arow = attn + ((size_t)b * S_ + qrow) * S_ + kt;
#pragma unroll
            for (int ni = 0; ni < 4; ni++) {
                float2 o = { acc[mi][ni][rr * 2 + 0], acc[mi][ni][rr * 2 + 1] };
                *(float2*)&arow[wn + ni * 8 + c * 2] = o;
            }
        }
    }
}

// =====================================================================
// Kernel 2: combine per-tile partials -> per-tile scale sc_t.
// One thread per row (32768 threads).
// =====================================================================
__global__ __launch_bounds__(256) void reduce_stats()
{
    const int row = blockIdx.x * 256 + threadIdx.x;   // b*S_ + qrow
    const float2* st = &g_stats[(size_t)row * NT_];
    float m = st[0].x;
#pragma unroll
    for (int t = 1; t < NT_; t++) m = fmaxf(m, st[t].x);
    float sum = 0.0f;
    float es[NT_];
#pragma unroll
    for (int t = 0; t < NT_; t++) {
        es[t] = __expf(st[t].x - m);
        sum += st[t].y * es[t];
    }
    const float inv = 1.0f / sum;
    float* sc = &g_scale[(size_t)row * NT_];
#pragma unroll
    for (int t = 0; t < NT_; t++) sc[t] = es[t] * inv;
}

// =====================================================================
// Kernel 3: normalize attn in place AND compute out = P @ V.
// p = e * sc_t; write p back; mma with p. fp16 m16n8k16.
// =====================================================================
__global__ __launch_bounds__(256, 2) void out_fused(
    float* __restrict__ attn, const float* __restrict__ v,
    float* __restrict__ out)
{
    __shared__ half Ph[128 * HLD_];
    __shared__ uint32_t Vs2[16 * VLD_];
    __shared__ float sc_s[128 * NT_];   // 8 KB

    const int b  = blockIdx.x;
    const int qt = blockIdx.y * 128;

    float* pb = attn + ((size_t)b * S_ + qt) * S_;
    const float* vb = v + (size_t)b * S_ * D_;

    const int tid  = threadIdx.x;
    const int wid  = tid >> 5, lane = tid & 31;
    const int g    = lane >> 2, c = lane & 3;
    const int wm   = (wid & 1) * 64;
    const int wn   = (wid >> 1) * 32;

    const int pr    = tid >> 4;
    const int dbase = (tid & 15) * 4;

    // load scales for this CTA's 128 rows (contiguous 8 KB)
    {
        const float4* src = (const float4*)&g_scale[((size_t)(b * S_ + qt)) * NT_];
        float4* dst = (float4*)sc_s;
        dst[tid]       = src[tid];
        dst[tid + 256] = src[tid + 256];
    }

    float acc[4][4][4];
#pragma unroll
    for (int mi = 0; mi < 4; mi++)
#pragma unroll
        for (int ni = 0; ni < 4; ni++)
#pragma unroll
            for (int r = 0; r < 4; r++) acc[mi][ni][r] = 0.0f;

    __syncthreads();

#pragma unroll 1
    for (int k0 = 0; k0 < S_; k0 += 32) {
        const int tile = k0 >> 7;
        // P fill: read e, scale, write back normalized, stash halves
#pragma unroll
        for (int t = 0; t < 4; t++) {
            const int idx = tid + t * 256;
            const int row = idx >> 3, c4 = (idx & 7) * 4;
            float4 vp = *(const float4*)&pb[(size_t)row * S_ + k0 + c4];
            const float sc = sc_s[row * NT_ + tile];
            vp.x *= sc; vp.y *= sc; vp.z *= sc; vp.w *= sc;
            *(float4*)&pb[(size_t)row * S_ + k0 + c4] = vp;
            store_perm(&Ph[row * HLD_], c4, vp);
        }
        // V fill: pack k-pairs into half2
        {
            const float* v0r = vb + (size_t)(k0 + 2 * pr) * D_;
            const float* v1r = v0r + D_;
#pragma unroll
            for (int h = 0; h < 2; h++) {
                const int d = dbase + h * 64;
                const float4 a = *(const float4*)&v0r[d];
                const float4 bb = *(const float4*)&v1r[d];
                uint4 u;
                u.x = h2u(__floats2half2_rn(a.x, bb.x));
                u.y = h2u(__floats2half2_rn(a.y, bb.y));
                u.z = h2u(__floats2half2_rn(a.z, bb.z));
                u.w = h2u(__floats2half2_rn(a.w, bb.w));
                *(uint4*)&Vs2[pr * VLD_ + d] = u;
            }
        }
        __syncthreads();

#pragma unroll
        for (int kq = 0; kq < 2; kq++) {
            const int co = kq * 16 + 4 * c;
            uint32_t bf[4][2];
#pragma unroll
            for (int ni = 0; ni < 4; ni++) {
                const int col = wn + ni * 8 + g;
                bf[ni][0] = Vs2[(kq * 8 + c)     * VLD_ + col];
                bf[ni][1] = Vs2[(kq * 8 + c + 4) * VLD_ + col];
            }
#pragma unroll
            for (int mi = 0; mi < 4; mi++) {
                const int row = wm + mi * 16 + g;
                const uint2 alo = *(const uint2*)&Ph[row * HLD_ + co];
                const uint2 ahi = *(const uint2*)&Ph[(row + 8) * HLD_ + co];
#pragma unroll
                for (int ni = 0; ni < 4; ni++)
                    mma16(acc[mi][ni], alo.x, ahi.x, alo.y, ahi.y, bf[ni][0], bf[ni][1]);
            }
        }
        __syncthreads();
    }

#pragma unroll
    for (int mi = 0; mi < 4; mi++) {
#pragma unroll
        for (int rr = 0; rr < 2; rr++) {
            const int qrow = qt + wm + mi * 16 + g + rr * 8;
            float* orow = out + ((size_t)b * S_ + qrow) * D_;
#pragma unroll
            for (int ni = 0; ni < 4; ni++) {
                const int col = wn + ni * 8 + c * 2;
                float2 o = { acc[mi][ni][rr * 2 + 0], acc[mi][ni][rr * 2 + 1] };
                *(float2*)&orow[col] = o;
            }
        }
    }
}

// =====================================================================
// d_out = [output (B*S*D) | attn (B*S*S)]
// =====================================================================
extern "C" void kernel_launch(void* const* d_in, const int* in_sizes, int n_in,
                              void* d_out, int out_size)
{
    const float* q    = (const float*)d_in[0];
    const float* k    = (const float*)d_in[1];
    const float* v    = (const float*)d_in[2];
    const float* mask = (const float*)d_in[3];

    float* out  = (float*)d_out;
    float* attn = out + (size_t)B_ * S_ * D_;

    dim3 g1(B_, S_ / 128, S_ / 128);
    scores_mma<<<g1, 256>>>(q, k, mask, attn);

    reduce_stats<<<(B_ * S_) / 256, 256>>>();

    dim3 g3(B_, S_ / 128);
    out_fused<<<g3, 256>>>(attn, v, out);
}

// round 10
// speedup vs baseline: 1.1233x; 1.1233x over previous
#include <cuda_runtime.h>
#include <cuda_fp16.h>
#include <cstdint>

#define B_ 16
#define S_ 2048
#define D_ 128
#define SCALE_ 0.08838834764831845f  // 1/sqrt(128)

#define HLD_ 40    // halves per Q/K/P smem row (32 data + 8 pad) -> LDSM conflict-free
#define VLDH_ 136  // halves per V smem row (128 data + 8 pad)   -> LDSM.trans conflict-free

__device__ __forceinline__ uint32_t h2u(half2 h) {
    union { half2 h; uint32_t u; } cvt;
    cvt.h = h;
    return cvt.u;
}

__device__ __forceinline__ uint32_t smem_u32(const void* p) {
    uint32_t a;
    asm("{ .reg .u64 t; cvta.to.shared.u64 t, %1; cvt.u32.u64 %0, t; }" : "=r"(a) : "l"(p));
    return a;
}

// D += A*B, m16n8k16 f16 (f32 accum)
__device__ __forceinline__ void mma16(float* d, uint32_t a0, uint32_t a1, uint32_t a2,
                                      uint32_t a3, uint32_t b0, uint32_t b1) {
    asm volatile(
        "mma.sync.aligned.m16n8k16.row.col.f32.f16.f16.f32 "
        "{%0,%1,%2,%3}, {%4,%5,%6,%7}, {%8,%9}, {%0,%1,%2,%3};"
        : "+f"(d[0]), "+f"(d[1]), "+f"(d[2]), "+f"(d[3])
        : "r"(a0), "r"(a1), "r"(a2), "r"(a3), "r"(b0), "r"(b1));
}

#define LDSM4(r0, r1, r2, r3, a) \
    asm volatile("ldmatrix.sync.aligned.m8n8.x4.shared.b16 {%0,%1,%2,%3}, [%4];" \
                 : "=r"(r0), "=r"(r1), "=r"(r2), "=r"(r3) : "r"(a))
#define LDSM4T(r0, r1, r2, r3, a) \
    asm volatile("ldmatrix.sync.aligned.m8n8.x4.trans.shared.b16 {%0,%1,%2,%3}, [%4];" \
                 : "=r"(r0), "=r"(r1), "=r"(r2), "=r"(r3) : "r"(a))

// Convert float4 -> 4 halves, store as one STS.64
__device__ __forceinline__ void store_h4(half* rowp, int c4, float4 v) {
    uint2 u = { h2u(__floats2half2_rn(v.x, v.y)), h2u(__floats2half2_rn(v.z, v.w)) };
    *(uint2*)(rowp + c4) = u;
}

// =====================================================================
// Kernel 1: scores[b,q,k] = (Q.K^T)*SCALE + mask
// CTA 128x128, BK=32. 8 warps = 2(m) x 4(n). fp16 m16n8k16 + ldmatrix.
// =====================================================================
__global__ __launch_bounds__(256, 2) void scores_mma(
    const float* __restrict__ q, const float* __restrict__ k,
    const float* __restrict__ mask, float* __restrict__ attn)
{
    __shared__ half Qh[128 * HLD_];
    __shared__ half Kh[128 * HLD_];

    const int b  = blockIdx.x;
    const int kt = blockIdx.y * 128;
    const int qt = blockIdx.z * 128;

    const float* qb = q + ((size_t)b * S_ + qt) * D_;
    const float* kb = k + ((size_t)b * S_ + kt) * D_;

    const int tid  = threadIdx.x;
    const int wid  = tid >> 5, lane = tid & 31;
    const int g    = lane >> 2, c = lane & 3;
    const int wm   = (wid & 1) * 64;
    const int wn   = (wid >> 1) * 32;

    const uint32_t qbase = smem_u32(Qh);
    const uint32_t kbase = smem_u32(Kh);
    const int l15 = lane & 15;            // row within 16
    const int khi = (lane >> 4) << 3;     // 0 or 8 (k-halves offset)

    float acc[4][4][4];
#pragma unroll
    for (int mi = 0; mi < 4; mi++)
#pragma unroll
        for (int ni = 0; ni < 4; ni++)
#pragma unroll
            for (int r = 0; r < 4; r++) acc[mi][ni][r] = 0.0f;

#pragma unroll 1
    for (int d0 = 0; d0 < D_; d0 += 32) {
#pragma unroll
        for (int t = 0; t < 4; t++) {
            const int idx = tid + t * 256;
            const int row = idx >> 3, c4 = (idx & 7) * 4;
            const float4 vq = *(const float4*)&qb[(size_t)row * D_ + d0 + c4];
            const float4 vk = *(const float4*)&kb[(size_t)row * D_ + d0 + c4];
            store_h4(&Qh[row * HLD_], c4, vq);
            store_h4(&Kh[row * HLD_], c4, vk);
        }
        __syncthreads();

#pragma unroll
        for (int kq = 0; kq < 2; kq++) {
            const int koff = kq * 16 + khi;
            uint32_t b0[4], b1[4];
#pragma unroll
            for (int bg = 0; bg < 2; bg++) {
                const uint32_t a = kbase +
                    (uint32_t)(((wn + bg * 16 + l15) * HLD_ + koff) << 1);
                LDSM4(b0[2 * bg], b0[2 * bg + 1], b1[2 * bg], b1[2 * bg + 1], a);
            }
#pragma unroll
            for (int mi = 0; mi < 4; mi++) {
                uint32_t a0, a1, a2, a3;
                const uint32_t a = qbase +
                    (uint32_t)(((wm + mi * 16 + l15) * HLD_ + koff) << 1);
                LDSM4(a0, a1, a2, a3, a);
#pragma unroll
                for (int ni = 0; ni < 4; ni++)
                    mma16(acc[mi][ni], a0, a1, a2, a3, b0[ni], b1[ni]);
            }
        }
        __syncthreads();
    }

    // Epilogue: scale + mask
#pragma unroll
    for (int mi = 0; mi < 4; mi++) {
#pragma unroll
        for (int rr = 0; rr < 2; rr++) {
            const int qrow = qt + wm + mi * 16 + g + rr * 8;
            const float* mrow = mask + (size_t)qrow * S_ + kt;
            float* arow = attn + ((size_t)b * S_ + qrow) * S_ + kt;
#pragma unroll
            for (int ni = 0; ni < 4; ni++) {
                const int col = wn + ni * 8 + c * 2;
                const float2 m2 = *(const float2*)&mrow[col];
                float2 o;
                o.x = acc[mi][ni][rr * 2 + 0] * SCALE_ + m2.x;
                o.y = acc[mi][ni][rr * 2 + 1] * SCALE_ + m2.y;
                *(float2*)&arow[col] = o;
            }
        }
    }
}

// =====================================================================
// Kernel 2: in-place row softmax. One 256-thread CTA per row.
// =====================================================================
__global__ __launch_bounds__(256) void softmax_kernel(float* __restrict__ attn)
{
    __shared__ float red[256];
    const size_t row = blockIdx.x;
    float* p = attn + row * (size_t)S_;
    const int tid = threadIdx.x;

    float4 v0 = ((const float4*)p)[tid];
    float4 v1 = ((const float4*)p)[tid + 256];

    float m = fmaxf(fmaxf(fmaxf(v0.x, v0.y), fmaxf(v0.z, v0.w)),
                    fmaxf(fmaxf(v1.x, v1.y), fmaxf(v1.z, v1.w)));
    red[tid] = m;
    __syncthreads();
#pragma unroll
    for (int s = 128; s > 0; s >>= 1) {
        if (tid < s) red[tid] = fmaxf(red[tid], red[tid + s]);
        __syncthreads();
    }
    m = red[0];
    __syncthreads();

    v0.x = __expf(v0.x - m); v0.y = __expf(v0.y - m);
    v0.z = __expf(v0.z - m); v0.w = __expf(v0.w - m);
    v1.x = __expf(v1.x - m); v1.y = __expf(v1.y - m);
    v1.z = __expf(v1.z - m); v1.w = __expf(v1.w - m);

    float sum = (v0.x + v0.y) + (v0.z + v0.w) + (v1.x + v1.y) + (v1.z + v1.w);
    red[tid] = sum;
    __syncthreads();
#pragma unroll
    for (int s = 128; s > 0; s >>= 1) {
        if (tid < s) red[tid] += red[tid + s];
        __syncthreads();
    }
    const float inv = 1.0f / red[0];

    v0.x *= inv; v0.y *= inv; v0.z *= inv; v0.w *= inv;
    v1.x *= inv; v1.y *= inv; v1.z *= inv; v1.w *= inv;
    ((float4*)p)[tid]       = v0;
    ((float4*)p)[tid + 256] = v1;
}

// =====================================================================
// Kernel 3: out[b,q,d] = sum_s P[b,q,s] * V[b,s,d]
// fp16 m16n8k16. P via ldmatrix; V via ldmatrix.trans from natural [k][d].
// =====================================================================
__global__ __launch_bounds__(256, 2) void out_mma(
    const float* __restrict__ attn, const float* __restrict__ v,
    float* __restrict__ out)
{
    __shared__ half Ph[128 * HLD_];
    __shared__ half Vh[32 * VLDH_];

    const int b  = blockIdx.x;
    const int qt = blockIdx.y * 128;

    const float* pb = attn + ((size_t)b * S_ + qt) * S_;
    const float* vb = v + (size_t)b * S_ * D_;

    const int tid  = threadIdx.x;
    const int wid  = tid >> 5, lane = tid & 31;
    const int g    = lane >> 2, c = lane & 3;
    const int wm   = (wid & 1) * 64;
    const int wn   = (wid >> 1) * 32;

    const uint32_t pbase = smem_u32(Ph);
    const uint32_t vbase = smem_u32(Vh);
    const int l15  = lane & 15;
    const int khi  = (lane >> 4) << 3;
    const int vrow = (lane & 7) + ((lane & 8) ? 8 : 0);   // k row within 16
    const int vnhi = (lane & 16) ? 8 : 0;                 // n offset 0/8

    float acc[4][4][4];
#pragma unroll
    for (int mi = 0; mi < 4; mi++)
#pragma unroll
        for (int ni = 0; ni < 4; ni++)
#pragma unroll
            for (int r = 0; r < 4; r++) acc[mi][ni][r] = 0.0f;

#pragma unroll 1
    for (int k0 = 0; k0 < S_; k0 += 32) {
        // P fill: 128 rows x 32 k
#pragma unroll
        for (int t = 0; t < 4; t++) {
            const int idx = tid + t * 256;
            const int row = idx >> 3, c4 = (idx & 7) * 4;
            const float4 vp = *(const float4*)&pb[(size_t)row * S_ + k0 + c4];
            store_h4(&Ph[row * HLD_], c4, vp);
        }
        // V fill: 32 k-rows x 128 d
#pragma unroll
        for (int t = 0; t < 4; t++) {
            const int idx = tid + t * 256;
            const int row = idx >> 5, c4 = (idx & 31) * 4;
            const float4 vv = *(const float4*)&vb[(size_t)(k0 + row) * D_ + c4];
            store_h4(&Vh[row * VLDH_], c4, vv);
        }
        __syncthreads();

#pragma unroll
        for (int kq = 0; kq < 2; kq++) {
            uint32_t b0[4], b1[4];
#pragma unroll
            for (int bg = 0; bg < 2; bg++) {
                const uint32_t a = vbase +
                    (uint32_t)(((kq * 16 + vrow) * VLDH_ + wn + bg * 16 + vnhi) << 1);
                LDSM4T(b0[2 * bg], b1[2 * bg], b0[2 * bg + 1], b1[2 * bg + 1], a);
            }
            const int koff = kq * 16 + khi;
#pragma unroll
            for (int mi = 0; mi < 4; mi++) {
                uint32_t a0, a1, a2, a3;
                const uint32_t a = pbase +
                    (uint32_t)(((wm + mi * 16 + l15) * HLD_ + koff) << 1);
                LDSM4(a0, a1, a2, a3, a);
#pragma unroll
                for (int ni = 0; ni < 4; ni++)
                    mma16(acc[mi][ni], a0, a1, a2, a3, b0[ni], b1[ni]);
            }
        }
        __syncthreads();
    }

#pragma unroll
    for (int mi = 0; mi < 4; mi++) {
#pragma unroll
        for (int rr = 0; rr < 2; rr++) {
            const int qrow = qt + wm + mi * 16 + g + rr * 8;
            float* orow = out + ((size_t)b * S_ + qrow) * D_;
#pragma unroll
            for (int ni = 0; ni < 4; ni++) {
                const int col = wn + ni * 8 + c * 2;
                float2 o = { acc[mi][ni][rr * 2 + 0], acc[mi][ni][rr * 2 + 1] };
                *(float2*)&orow[col] = o;
            }
        }
    }
}

// =====================================================================
// d_out = [output (B*S*D) | attn (B*S*S)]
// =====================================================================
extern "C" void kernel_launch(void* const* d_in, const int* in_sizes, int n_in,
                              void* d_out, int out_size)
{
    const float* q    = (const float*)d_in[0];
    const float* k    = (const float*)d_in[1];
    const float* v    = (const float*)d_in[2];
    const float* mask = (const float*)d_in[3];

    float* out  = (float*)d_out;
    float* attn = out + (size_t)B_ * S_ * D_;

    dim3 g1(B_, S_ / 128, S_ / 128);   // b fastest -> L2 reuse of Q/K/mask tiles
    scores_mma<<<g1, 256>>>(q, k, mask, attn);

    softmax_kernel<<<B_ * S_, 256>>>(attn);

    dim3 g3(B_, S_ / 128);
    out_mma<<<g3, 256>>>(attn, v, out);
}

// round 11
// speedup vs baseline: 1.3000x; 1.1573x over previous
#include <cuda_runtime.h>
#include <cuda_fp16.h>
#include <cstdint>

#define B_ 16
#define S_ 2048
#define D_ 128
#define SCALE_ 0.08838834764831845f  // 1/sqrt(128)

#define QLD_ 136   // halves per Q/K smem row (128 data + 8 pad)
#define HLD_ 48    // halves per P smem row (32 data + 16 pad) = 24 words (round-8)
#define VLD_ 136   // words per Vs2 row (128 data + 8 pad)      (round-8)

__device__ __forceinline__ uint32_t h2u(half2 h) {
    union { half2 h; uint32_t u; } cvt;
    cvt.h = h;
    return cvt.u;
}

__device__ __forceinline__ uint32_t smem_u32(const void* p) {
    uint32_t a;
    asm("{ .reg .u64 t; cvta.to.shared.u64 t, %1; cvt.u32.u64 %0, t; }" : "=r"(a) : "l"(p));
    return a;
}

// D += A*B, m16n8k16 f16 (f32 accum)
__device__ __forceinline__ void mma16(float* d, uint32_t a0, uint32_t a1, uint32_t a2,
                                      uint32_t a3, uint32_t b0, uint32_t b1) {
    asm volatile(
        "mma.sync.aligned.m16n8k16.row.col.f32.f16.f16.f32 "
        "{%0,%1,%2,%3}, {%4,%5,%6,%7}, {%8,%9}, {%0,%1,%2,%3};"
        : "+f"(d[0]), "+f"(d[1]), "+f"(d[2]), "+f"(d[3])
        : "r"(a0), "r"(a1), "r"(a2), "r"(a3), "r"(b0), "r"(b1));
}

#define LDSM4(r0, r1, r2, r3, a) \
    asm volatile("ldmatrix.sync.aligned.m8n8.x4.shared.b16 {%0,%1,%2,%3}, [%4];" \
                 : "=r"(r0), "=r"(r1), "=r"(r2), "=r"(r3) : "r"(a))

// Convert float4 -> 4 halves, one STS.64
__device__ __forceinline__ void store_h4(half* rowp, int c4, float4 v) {
    uint2 u = { h2u(__floats2half2_rn(v.x, v.y)), h2u(__floats2half2_rn(v.z, v.w)) };
    *(uint2*)(rowp + c4) = u;
}

// Permuted half store (round-8 out_mma P layout)
__device__ __forceinline__ void store_perm(half* rowp, int c4, float4 v) {
    const int kk0 = c4 & 15;
    const int pos = ((c4 >> 4) << 4) + ((kk0 & 7) << 1) + ((kk0 >> 3) << 1);
    *(half2*)(rowp + pos)     = __floats2half2_rn(v.x, v.y);
    *(half2*)(rowp + pos + 4) = __floats2half2_rn(v.z, v.w);
}

// =====================================================================
// Kernel 1: scores[b,q,k] = (Q.K^T)*SCALE + mask
// CTA 128x128. FULL-DEPTH tiles: one smem fill, ONE barrier, then 8
// uninterrupted k-steps of LDSM + mma. 8 warps = 2(m) x 4(n).
// =====================================================================
#define S_SMEM (2 * 128 * QLD_ * 2)   // 69632 B dynamic

__global__ __launch_bounds__(256, 2) void scores_mma(
    const float* __restrict__ q, const float* __restrict__ k,
    const float* __restrict__ mask, float* __restrict__ attn)
{
    extern __shared__ half sm[];
    half* Qh = sm;                 // [128][QLD_]
    half* Kh = sm + 128 * QLD_;    // [128][QLD_]

    const int b  = blockIdx.x;
    const int kt = blockIdx.y * 128;
    const int qt = blockIdx.z * 128;

    const float* qb = q + ((size_t)b * S_ + qt) * D_;
    const float* kb = k + ((size_t)b * S_ + kt) * D_;

    const int tid  = threadIdx.x;
    const int wid  = tid >> 5, lane = tid & 31;
    const int g    = lane >> 2, c = lane & 3;
    const int wm   = (wid & 1) * 64;
    const int wn   = (wid >> 1) * 32;

    const uint32_t qbase = smem_u32(Qh);
    const uint32_t kbase = smem_u32(Kh);
    const int l15 = lane & 15;
    const int khi = (lane >> 4) << 3;

    float acc[4][4][4];
#pragma unroll
    for (int mi = 0; mi < 4; mi++)
#pragma unroll
        for (int ni = 0; ni < 4; ni++)
#pragma unroll
            for (int r = 0; r < 4; r++) acc[mi][ni][r] = 0.0f;

    // ---- single fill: full 128x128 Q and K tiles ----
#pragma unroll
    for (int t = 0; t < 16; t++) {
        const int idx = tid + t * 256;
        const int row = idx >> 5, c4 = (idx & 31) * 4;
        const float4 vq = *(const float4*)&qb[(size_t)row * D_ + c4];
        store_h4(&Qh[row * QLD_], c4, vq);
    }
#pragma unroll
    for (int t = 0; t < 16; t++) {
        const int idx = tid + t * 256;
        const int row = idx >> 5, c4 = (idx & 31) * 4;
        const float4 vk = *(const float4*)&kb[(size_t)row * D_ + c4];
        store_h4(&Kh[row * QLD_], c4, vk);
    }
    __syncthreads();

    // ---- 8 k-steps, no barriers ----
#pragma unroll
    for (int kq = 0; kq < 8; kq++) {
        const int koff = kq * 16 + khi;
        uint32_t b0[4], b1[4];
#pragma unroll
        for (int bg = 0; bg < 2; bg++) {
            const uint32_t a = kbase +
                (uint32_t)(((wn + bg * 16 + l15) * QLD_ + koff) << 1);
            LDSM4(b0[2 * bg], b0[2 * bg + 1], b1[2 * bg], b1[2 * bg + 1], a);
        }
#pragma unroll
        for (int mi = 0; mi < 4; mi++) {
            uint32_t a0, a1, a2, a3;
            const uint32_t a = qbase +
                (uint32_t)(((wm + mi * 16 + l15) * QLD_ + koff) << 1);
            LDSM4(a0, a1, a2, a3, a);
#pragma unroll
            for (int ni = 0; ni < 4; ni++)
                mma16(acc[mi][ni], a0, a1, a2, a3, b0[ni], b1[ni]);
        }
    }

    // ---- epilogue: scale + mask ----
#pragma unroll
    for (int mi = 0; mi < 4; mi++) {
#pragma unroll
        for (int rr = 0; rr < 2; rr++) {
            const int qrow = qt + wm + mi * 16 + g + rr * 8;
            const float* mrow = mask + (size_t)qrow * S_ + kt;
            float* arow = attn + ((size_t)b * S_ + qrow) * S_ + kt;
#pragma unroll
            for (int ni = 0; ni < 4; ni++) {
                const int col = wn + ni * 8 + c * 2;
                const float2 m2 = *(const float2*)&mrow[col];
                float2 o;
                o.x = acc[mi][ni][rr * 2 + 0] * SCALE_ + m2.x;
                o.y = acc[mi][ni][rr * 2 + 1] * SCALE_ + m2.y;
                *(float2*)&arow[col] = o;
            }
        }
    }
}

// =====================================================================
// Kernel 2: in-place row softmax. One 256-thread CTA per row.
// =====================================================================
__global__ __launch_bounds__(256) void softmax_kernel(float* __restrict__ attn)
{
    __shared__ float red[256];
    const size_t row = blockIdx.x;
    float* p = attn + row * (size_t)S_;
    const int tid = threadIdx.x;

    float4 v0 = ((const float4*)p)[tid];
    float4 v1 = ((const float4*)p)[tid + 256];

    float m = fmaxf(fmaxf(fmaxf(v0.x, v0.y), fmaxf(v0.z, v0.w)),
                    fmaxf(fmaxf(v1.x, v1.y), fmaxf(v1.z, v1.w)));
    red[tid] = m;
    __syncthreads();
#pragma unroll
    for (int s = 128; s > 0; s >>= 1) {
        if (tid < s) red[tid] = fmaxf(red[tid], red[tid + s]);
        __syncthreads();
    }
    m = red[0];
    __syncthreads();

    v0.x = __expf(v0.x - m); v0.y = __expf(v0.y - m);
    v0.z = __expf(v0.z - m); v0.w = __expf(v0.w - m);
    v1.x = __expf(v1.x - m); v1.y = __expf(v1.y - m);
    v1.z = __expf(v1.z - m); v1.w = __expf(v1.w - m);

    float sum = (v0.x + v0.y) + (v0.z + v0.w) + (v1.x + v1.y) + (v1.z + v1.w);
    red[tid] = sum;
    __syncthreads();
#pragma unroll
    for (int s = 128; s > 0; s >>= 1) {
        if (tid < s) red[tid] += red[tid + s];
        __syncthreads();
    }
    const float inv = 1.0f / red[0];

    v0.x *= inv; v0.y *= inv; v0.z *= inv; v0.w *= inv;
    v1.x *= inv; v1.y *= inv; v1.z *= inv; v1.w *= inv;
    ((float4*)p)[tid]       = v0;
    ((float4*)p)[tid + 256] = v1;
}

// =====================================================================
// Kernel 3: out[b,q,d] = sum_s P[b,q,s] * V[b,s,d]   (round-8 exact)
// fp16 m16n8k16. P permuted; V packed as half2 k-pairs.
// =====================================================================
__global__ __launch_bounds__(256, 2) void out_mma(
    const float* __restrict__ attn, const float* __restrict__ v,
    float* __restrict__ out)
{
    __shared__ half Ph[128 * HLD_];
    __shared__ uint32_t Vs2[16 * VLD_];

    const int b  = blockIdx.x;
    const int qt = blockIdx.y * 128;

    const float* pb = attn + ((size_t)b * S_ + qt) * S_;
    const float* vb = v + (size_t)b * S_ * D_;

    const int tid  = threadIdx.x;
    const int wid  = tid >> 5, lane = tid & 31;
    const int g    = lane >> 2, c = lane & 3;
    const int wm   = (wid & 1) * 64;
    const int wn   = (wid >> 1) * 32;

    const int pr    = tid >> 4;         // pair row 0..15
    const int dbase = (tid & 15) * 4;

    float acc[4][4][4];
#pragma unroll
    for (int mi = 0; mi < 4; mi++)
#pragma unroll
        for (int ni = 0; ni < 4; ni++)
#pragma unroll
            for (int r = 0; r < 4; r++) acc[mi][ni][r] = 0.0f;

#pragma unroll 1
    for (int k0 = 0; k0 < S_; k0 += 32) {
#pragma unroll
        for (int t = 0; t < 4; t++) {
            const int idx = tid + t * 256;
            const int row = idx >> 3, c4 = (idx & 7) * 4;
            const float4 vp = *(const float4*)&pb[(size_t)row * S_ + k0 + c4];
            store_perm(&Ph[row * HLD_], c4, vp);
        }
        {
            const float* v0r = vb + (size_t)(k0 + 2 * pr) * D_;
            const float* v1r = v0r + D_;
#pragma unroll
            for (int h = 0; h < 2; h++) {
                const int d = dbase + h * 64;
                const float4 a = *(const float4*)&v0r[d];
                const float4 bb = *(const float4*)&v1r[d];
                uint4 u;
                u.x = h2u(__floats2half2_rn(a.x, bb.x));
                u.y = h2u(__floats2half2_rn(a.y, bb.y));
                u.z = h2u(__floats2half2_rn(a.z, bb.z));
                u.w = h2u(__floats2half2_rn(a.w, bb.w));
                *(uint4*)&Vs2[pr * VLD_ + d] = u;
            }
        }
        __syncthreads();

#pragma unroll
        for (int kq = 0; kq < 2; kq++) {
            const int co = kq * 16 + 4 * c;
            uint32_t bf[4][2];
#pragma unroll
            for (int ni = 0; ni < 4; ni++) {
                const int col = wn + ni * 8 + g;
                bf[ni][0] = Vs2[(kq * 8 + c)     * VLD_ + col];
                bf[ni][1] = Vs2[(kq * 8 + c + 4) * VLD_ + col];
            }
#pragma unroll
            for (int mi = 0; mi < 4; mi++) {
                const int row = wm + mi * 16 + g;
                const uint2 alo = *(const uint2*)&Ph[row * HLD_ + co];
                const uint2 ahi = *(const uint2*)&Ph[(row + 8) * HLD_ + co];
#pragma unroll
                for (int ni = 0; ni < 4; ni++)
                    mma16(acc[mi][ni], alo.x, ahi.x, alo.y, ahi.y, bf[ni][0], bf[ni][1]);
            }
        }
        __syncthreads();
    }

#pragma unroll
    for (int mi = 0; mi < 4; mi++) {
#pragma unroll
        for (int rr = 0; rr < 2; rr++) {
            const int qrow = qt + wm + mi * 16 + g + rr * 8;
            float* orow = out + ((size_t)b * S_ + qrow) * D_;
#pragma unroll
            for (int ni = 0; ni < 4; ni++) {
                const int col = wn + ni * 8 + c * 2;
                float2 o = { acc[mi][ni][rr * 2 + 0], acc[mi][ni][rr * 2 + 1] };
                *(float2*)&orow[col] = o;
            }
        }
    }
}

// =====================================================================
// d_out = [output (B*S*D) | attn (B*S*S)]
// =====================================================================
extern "C" void kernel_launch(void* const* d_in, const int* in_sizes, int n_in,
                              void* d_out, int out_size)
{
    const float* q    = (const float*)d_in[0];
    const float* k    = (const float*)d_in[1];
    const float* v    = (const float*)d_in[2];
    const float* mask = (const float*)d_in[3];

    float* out  = (float*)d_out;
    float* attn = out + (size_t)B_ * S_ * D_;

    cudaFuncSetAttribute(scores_mma, cudaFuncAttributeMaxDynamicSharedMemorySize, S_SMEM);

    dim3 g1(B_, S_ / 128, S_ / 128);   // b fastest -> L2 reuse of Q/K/mask tiles
    scores_mma<<<g1, 256, S_SMEM>>>(q, k, mask, attn);

    softmax_kernel<<<B_ * S_, 256>>>(attn);

    dim3 g3(B_, S_ / 128);
    out_mma<<<g3, 256>>>(attn, v, out);
}